// round 4
// baseline (speedup 1.0000x reference)
#include <cuda_runtime.h>
#include <cuda_bf16.h>
#include <math.h>

// Problem constants (fixed by the reference)
#define NN 50000
#define EE 800000
#define FIN 128
#define ED 16
#define H1 8
#define C1 8
#define HID 64      // H1*C1
#define OUT 128
#define GG 256
#define NEG 0.2f

// ---------------- device scratch (static, allocation-free) ----------------
__device__ int   g_deg[NN];
__device__ int   g_ptr[NN + 1];
__device__ int   g_cursor[NN];
__device__ int   g_src[EE];
__device__ int   g_eid[EE];
__device__ float g_alE1[EE * 8];     // per CSR slot, 8 heads
__device__ float g_alE2[EE];         // per CSR slot, 1 head
__device__ float g_alE1s[NN * 8];    // self-loop attn (layer1)
__device__ float g_alE2s[NN];        // self-loop attn (layer2)
__device__ float g_xw1[NN * HID];
__device__ float g_als1[NN * 8];
__device__ float g_ald1[NN * 8];
__device__ float g_h[NN * HID];      // layer1 output (post ELU)
__device__ float g_xw2[NN * OUT];
__device__ float g_als2[NN];
__device__ float g_ald2[NN];
__device__ float g_out2[NN * OUT];
__device__ float g_M1[ED * 8];       // We1 reduced by att_edge1
__device__ float g_m2[ED];           // We2 reduced by att_edge2
__device__ int   g_gptr[GG + 1];

// ---------------- kernels ----------------

__global__ void zero_deg_kernel() {
    int i = blockIdx.x * blockDim.x + threadIdx.x;
    if (i < NN) g_deg[i] = 0;
}

__global__ void deg_kernel(const int* __restrict__ ei) {
    int e = blockIdx.x * blockDim.x + threadIdx.x;
    if (e < EE) {
        int d = ei[EE + e];
        atomicAdd(&g_deg[d], 1);
    }
}

// Exclusive prefix sum of g_deg -> g_ptr, g_cursor. Single block, 1024 threads.
__global__ void scan_kernel() {
    const int IT = 49;  // 1024*49 = 50176 >= NN
    int t = threadIdx.x;
    int base = t * IT;
    int sum = 0;
    for (int k = 0; k < IT; k++) {
        int i = base + k;
        if (i < NN) sum += g_deg[i];
    }
    int incl = sum;
    #pragma unroll
    for (int o = 1; o < 32; o <<= 1) {
        int u = __shfl_up_sync(0xffffffffu, incl, o);
        if ((t & 31) >= o) incl += u;
    }
    __shared__ int ws[32];
    if ((t & 31) == 31) ws[t >> 5] = incl;
    __syncthreads();
    if (t < 32) {
        int wv = ws[t];
        int wincl = wv;
        #pragma unroll
        for (int o = 1; o < 32; o <<= 1) {
            int u = __shfl_up_sync(0xffffffffu, wincl, o);
            if (t >= o) wincl += u;
        }
        ws[t] = wincl - wv;  // exclusive warp offset
    }
    __syncthreads();
    int run = ws[t >> 5] + (incl - sum);
    for (int k = 0; k < IT; k++) {
        int i = base + k;
        if (i < NN) {
            g_ptr[i] = run;
            g_cursor[i] = run;
            run += g_deg[i];
        }
    }
    if (t == 0) g_ptr[NN] = EE;
}

__global__ void scatter_kernel(const int* __restrict__ ei) {
    int e = blockIdx.x * blockDim.x + threadIdx.x;
    if (e < EE) {
        int s = ei[e];
        int d = ei[EE + e];
        int pos = atomicAdd(&g_cursor[d], 1);
        g_src[pos] = s;
        g_eid[pos] = e;
    }
}

// Precompute M1[d,h] = sum_c We1[d,h*8+c]*att_edge1[h,c]; m2[d] = sum_c We2[d,c]*att_edge2[c]
__global__ void prep_attn_kernel(const float* __restrict__ We1, const float* __restrict__ ae1,
                                 const float* __restrict__ We2, const float* __restrict__ ae2) {
    int t = threadIdx.x;
    if (t < 128) {
        int d = t >> 3, h = t & 7;
        float s = 0.f;
        #pragma unroll
        for (int c = 0; c < 8; c++) s += We1[d * 64 + h * 8 + c] * ae1[h * 8 + c];
        g_M1[d * 8 + h] = s;
    }
    if (t < ED) {
        float s = 0.f;
        for (int c = 0; c < OUT; c++) s += We2[t * OUT + c] * ae2[c];
        g_m2[t] = s;
    }
}

// xw1 = x @ W1, plus per-node attention scalars als1/ald1. 16 nodes per 256-thread block.
__global__ void gemm1_kernel(const float* __restrict__ x, const float* __restrict__ W1,
                             const float* __restrict__ as1, const float* __restrict__ ad1) {
    __shared__ float xs[16][FIN];
    int n0 = blockIdx.x * 16;
    for (int idx = threadIdx.x; idx < 16 * FIN; idx += 256)
        xs[idx >> 7][idx & 127] = x[(size_t)(n0 + (idx >> 7)) * FIN + (idx & 127)];
    __syncthreads();
    int jg = threadIdx.x & 15;   // float4 column group (4 of 64 outputs)
    int nd = threadIdx.x >> 4;   // node within block
    const float4* W1v = (const float4*)W1;
    float4 acc = make_float4(0.f, 0.f, 0.f, 0.f);
    #pragma unroll 4
    for (int k = 0; k < FIN; k++) {
        float xv = xs[nd][k];
        float4 w = W1v[k * 16 + jg];
        acc.x += xv * w.x; acc.y += xv * w.y; acc.z += xv * w.z; acc.w += xv * w.w;
    }
    int n = n0 + nd;
    ((float4*)g_xw1)[n * 16 + jg] = acc;
    float4 a_s = ((const float4*)as1)[jg];
    float4 a_d = ((const float4*)ad1)[jg];
    float ps = acc.x * a_s.x + acc.y * a_s.y + acc.z * a_s.z + acc.w * a_s.w;
    float pd = acc.x * a_d.x + acc.y * a_d.y + acc.z * a_d.z + acc.w * a_d.w;
    ps += __shfl_xor_sync(0xffffffffu, ps, 1);
    pd += __shfl_xor_sync(0xffffffffu, pd, 1);
    if ((threadIdx.x & 1) == 0) {
        int h = jg >> 1;
        g_als1[n * 8 + h] = ps;
        g_ald1[n * 8 + h] = pd;
    }
}

// Per-CSR-slot edge attention logits from edge_attr (one read of edge_attr, ever).
__global__ void alE_kernel(const float* __restrict__ ea) {
    __shared__ float sM1[ED * 8];
    __shared__ float sm2[ED];
    if (threadIdx.x < 128) sM1[threadIdx.x] = g_M1[threadIdx.x];
    if (threadIdx.x < ED) sm2[threadIdx.x] = g_m2[threadIdx.x];
    __syncthreads();
    int j = blockIdx.x * blockDim.x + threadIdx.x;
    if (j >= EE) return;
    int e = g_eid[j];
    const float4* p = (const float4*)(ea + (size_t)e * ED);
    float4 q0 = p[0], q1 = p[1], q2 = p[2], q3 = p[3];
    float av[16] = {q0.x, q0.y, q0.z, q0.w, q1.x, q1.y, q1.z, q1.w,
                    q2.x, q2.y, q2.z, q2.w, q3.x, q3.y, q3.z, q3.w};
    float r[8] = {0, 0, 0, 0, 0, 0, 0, 0};
    float r2 = 0.f;
    #pragma unroll
    for (int d = 0; d < ED; d++) {
        float a = av[d];
        #pragma unroll
        for (int h = 0; h < 8; h++) r[h] += a * sM1[d * 8 + h];
        r2 += a * sm2[d];
    }
    float4* o = (float4*)(g_alE1 + (size_t)j * 8);
    o[0] = make_float4(r[0], r[1], r[2], r[3]);
    o[1] = make_float4(r[4], r[5], r[6], r[7]);
    g_alE2[j] = r2;
}

// Self-loop attention logits by linearity: alE_self = (sum incoming alE)/max(deg,1)
__global__ void selfE_kernel() {
    int t = blockIdx.x * blockDim.x + threadIdx.x;
    int n = t >> 3;
    int h = t & 7;
    if (n >= NN) return;
    int beg = g_ptr[n], end = g_ptr[n + 1];
    float s1 = 0.f, s2 = 0.f;
    for (int j = beg; j < end; j++) {
        s1 += g_alE1[(size_t)j * 8 + h];
        if (h == 0) s2 += g_alE2[j];
    }
    float rd = 1.f / (float)max(end - beg, 1);
    g_alE1s[n * 8 + h] = s1 * rd;
    if (h == 0) g_alE2s[n] = s2 * rd;
}

// Layer-1 softmax + aggregation: one warp per node, online (no atomics, no max-sub).
// Each lane computes logits for head h8=l&7 over ALL edges, so each lane's `s`
// is already the COMPLETE per-head softmax denominator (4 redundant replicas).
__global__ void agg1_kernel(const float* __restrict__ b1) {
    int warp = (blockIdx.x * blockDim.x + threadIdx.x) >> 5;
    if (warp >= NN) return;
    int n = warp;
    int l = threadIdx.x & 31;
    int h8 = l & 7;
    int h0 = l >> 3;
    int h1 = h0 + 4;
    float ald = g_ald1[n * 8 + h8];
    // self loop
    float z = g_als1[n * 8 + h8] + ald + g_alE1s[n * 8 + h8];
    z = z > 0.f ? z : NEG * z;
    float e = __expf(z);
    float s = e;
    float a0 = __shfl_sync(0xffffffffu, e, h0);
    float a1 = __shfl_sync(0xffffffffu, e, h1);
    float acc0 = g_xw1[(size_t)n * 64 + l] * a0;
    float acc1 = g_xw1[(size_t)n * 64 + 32 + l] * a1;
    int beg = g_ptr[n], end = g_ptr[n + 1];
    for (int j = beg; j < end; j++) {
        int src = g_src[j];
        float zz = g_als1[src * 8 + h8] + ald + g_alE1[(size_t)j * 8 + h8];
        zz = zz > 0.f ? zz : NEG * zz;
        float ee = __expf(zz);
        s += ee;
        float w0 = __shfl_sync(0xffffffffu, ee, h0);
        float w1 = __shfl_sync(0xffffffffu, ee, h1);
        acc0 += g_xw1[(size_t)src * 64 + l] * w0;
        acc1 += g_xw1[(size_t)src * 64 + 32 + l] * w1;
    }
    // NOTE: s is already the full per-head sum (every lane walked every edge).
    // Lane h0 holds head h0's denominator; lane h1 holds head h1's.
    float s0 = __shfl_sync(0xffffffffu, s, h0);
    float s1 = __shfl_sync(0xffffffffu, s, h1);
    float o0 = acc0 / (s0 + 1e-16f) + b1[l];
    float o1 = acc1 / (s1 + 1e-16f) + b1[32 + l];
    o0 = o0 > 0.f ? o0 : (__expf(o0) - 1.f);   // ELU
    o1 = o1 > 0.f ? o1 : (__expf(o1) - 1.f);
    g_h[(size_t)n * 64 + l] = o0;
    g_h[(size_t)n * 64 + 32 + l] = o1;
}

// xw2 = h @ W2, plus als2/ald2. 8 nodes per 256-thread block (one warp per node).
__global__ void gemm2_kernel(const float* __restrict__ W2,
                             const float* __restrict__ as2, const float* __restrict__ ad2) {
    __shared__ float hs[8][HID];
    int n0 = blockIdx.x * 8;
    for (int idx = threadIdx.x; idx < 8 * HID; idx += 256)
        hs[idx >> 6][idx & 63] = g_h[(size_t)(n0 + (idx >> 6)) * HID + (idx & 63)];
    __syncthreads();
    int jg = threadIdx.x & 31;  // float4 group of 128 outputs
    int nd = threadIdx.x >> 5;  // node = warp
    const float4* W2v = (const float4*)W2;
    float4 acc = make_float4(0.f, 0.f, 0.f, 0.f);
    #pragma unroll 4
    for (int k = 0; k < HID; k++) {
        float hv = hs[nd][k];
        float4 w = W2v[k * 32 + jg];
        acc.x += hv * w.x; acc.y += hv * w.y; acc.z += hv * w.z; acc.w += hv * w.w;
    }
    int n = n0 + nd;
    ((float4*)g_xw2)[n * 32 + jg] = acc;
    float4 a_s = ((const float4*)as2)[jg];
    float4 a_d = ((const float4*)ad2)[jg];
    float ps = acc.x * a_s.x + acc.y * a_s.y + acc.z * a_s.z + acc.w * a_s.w;
    float pd = acc.x * a_d.x + acc.y * a_d.y + acc.z * a_d.z + acc.w * a_d.w;
    #pragma unroll
    for (int o = 16; o > 0; o >>= 1) {
        ps += __shfl_xor_sync(0xffffffffu, ps, o);
        pd += __shfl_xor_sync(0xffffffffu, pd, o);
    }
    if (jg == 0) {
        g_als2[n] = ps;
        g_ald2[n] = pd;
    }
}

// Layer-2 softmax + aggregation: one warp per node; lane owns 4 features (float4).
__global__ void agg2_kernel(const float* __restrict__ b2) {
    int warp = (blockIdx.x * blockDim.x + threadIdx.x) >> 5;
    if (warp >= NN) return;
    int n = warp;
    int l = threadIdx.x & 31;
    const float4* xw = (const float4*)g_xw2;
    float ald = g_ald2[n];
    float z = g_als2[n] + ald + g_alE2s[n];
    z = z > 0.f ? z : NEG * z;
    float e = __expf(z);
    float s = e;
    float4 v = xw[(size_t)n * 32 + l];
    float4 acc = make_float4(v.x * e, v.y * e, v.z * e, v.w * e);
    int beg = g_ptr[n], end = g_ptr[n + 1];
    for (int j = beg; j < end; j++) {
        int src = g_src[j];
        float zz = g_als2[src] + ald + g_alE2[j];
        zz = zz > 0.f ? zz : NEG * zz;
        float ee = __expf(zz);
        s += ee;
        float4 u = xw[(size_t)src * 32 + l];
        acc.x += u.x * ee; acc.y += u.y * ee; acc.z += u.z * ee; acc.w += u.w * ee;
    }
    float inv = 1.f / (s + 1e-16f);
    float4 bb = ((const float4*)b2)[l];
    float4 o = make_float4(acc.x * inv + bb.x, acc.y * inv + bb.y,
                           acc.z * inv + bb.z, acc.w * inv + bb.w);
    ((float4*)g_out2)[(size_t)n * 32 + l] = o;
}

// batch is sorted -> graph start offsets by binary search.
__global__ void gptr_kernel(const int* __restrict__ batch) {
    int g = blockIdx.x * blockDim.x + threadIdx.x;
    if (g > GG) return;
    if (g == GG) { g_gptr[GG] = NN; return; }
    int lo = 0, hi = NN;
    while (lo < hi) {
        int mid = (lo + hi) >> 1;
        if (batch[mid] < g) lo = mid + 1; else hi = mid;
    }
    g_gptr[g] = lo;
}

// Global mean pool: one block per graph, thread per feature.
__global__ void pool_kernel(float* __restrict__ out) {
    int g = blockIdx.x;
    int f = threadIdx.x;
    int s = g_gptr[g], e = g_gptr[g + 1];
    float acc = 0.f;
    for (int n = s; n < e; n++) acc += g_out2[(size_t)n * OUT + f];
    out[g * OUT + f] = acc / fmaxf((float)(e - s), 1.f);
}

// ---------------- launch ----------------
extern "C" void kernel_launch(void* const* d_in, const int* in_sizes, int n_in,
                              void* d_out, int out_size) {
    const float* x     = (const float*)d_in[0];
    const int*   ei    = (const int*)d_in[1];
    const float* ea    = (const float*)d_in[2];
    const int*   batch = (const int*)d_in[3];
    const float* W1    = (const float*)d_in[4];
    const float* as1   = (const float*)d_in[5];
    const float* ad1   = (const float*)d_in[6];
    const float* ae1   = (const float*)d_in[7];
    const float* We1   = (const float*)d_in[8];
    const float* b1    = (const float*)d_in[9];
    const float* W2    = (const float*)d_in[10];
    const float* as2   = (const float*)d_in[11];
    const float* ad2   = (const float*)d_in[12];
    const float* ae2   = (const float*)d_in[13];
    const float* We2   = (const float*)d_in[14];
    const float* b2    = (const float*)d_in[15];
    float* out = (float*)d_out;

    zero_deg_kernel<<<(NN + 255) / 256, 256>>>();
    deg_kernel<<<(EE + 255) / 256, 256>>>(ei);
    scan_kernel<<<1, 1024>>>();
    scatter_kernel<<<(EE + 255) / 256, 256>>>(ei);
    prep_attn_kernel<<<1, 128>>>(We1, ae1, We2, ae2);
    gemm1_kernel<<<NN / 16, 256>>>(x, W1, as1, ad1);
    alE_kernel<<<(EE + 255) / 256, 256>>>(ea);
    selfE_kernel<<<(NN * 8 + 255) / 256, 256>>>();
    agg1_kernel<<<NN / 8, 256>>>(b1);
    gemm2_kernel<<<NN / 8, 256>>>(W2, as2, ad2);
    agg2_kernel<<<NN / 8, 256>>>(b2);
    gptr_kernel<<<1, 512>>>(batch);
    pool_kernel<<<GG, OUT>>>(out);
}

// round 5
// speedup vs baseline: 1.0968x; 1.0968x over previous
#include <cuda_runtime.h>
#include <cuda_bf16.h>
#include <math.h>

// Problem constants (fixed by the reference)
#define NN 50000
#define EE 800000
#define FIN 128
#define ED 16
#define H1 8
#define C1 8
#define HID 64      // H1*C1
#define OUT 128
#define GG 256
#define NEG 0.2f

// ---------------- device scratch (static, allocation-free) ----------------
__device__ int   g_deg[NN];
__device__ int   g_ptr[NN + 1];
__device__ int   g_cursor[NN];
__device__ int   g_src[EE];
__device__ int   g_eid[EE];
__device__ float g_alE1[EE * 8];     // per CSR slot, 8 heads (layer-1 edge logit)
__device__ float g_alE2[EE];         // per CSR slot (layer-2 edge logit)
__device__ float g_xw1[NN * HID];
__device__ float g_als1[NN * 8];
__device__ float g_ald1[NN * 8];
__device__ float g_xw2[NN * OUT];
__device__ float g_als2[NN];
__device__ float g_ald2[NN];
__device__ float g_out2[NN * OUT];
__device__ float g_M1[ED * 8];       // We1 reduced by att_edge1
__device__ float g_m2[ED];           // We2 reduced by att_edge2
__device__ int   g_gptr[GG + 1];

// ---------------- kernels ----------------

// Fused setup: zero deg + reduced attention matrices + graph offsets.
__global__ void setup_kernel(const float* __restrict__ We1, const float* __restrict__ ae1,
                             const float* __restrict__ We2, const float* __restrict__ ae2,
                             const int* __restrict__ batch) {
    int i = blockIdx.x * blockDim.x + threadIdx.x;
    if (i < NN) g_deg[i] = 0;
    if (i < 128) {
        int d = i >> 3, h = i & 7;
        float s = 0.f;
        #pragma unroll
        for (int c = 0; c < 8; c++) s += We1[d * 64 + h * 8 + c] * ae1[h * 8 + c];
        g_M1[d * 8 + h] = s;
    }
    if (i < ED) {
        float s = 0.f;
        for (int c = 0; c < OUT; c++) s += We2[i * OUT + c] * ae2[c];
        g_m2[i] = s;
    }
    if (i <= GG) {
        if (i == GG) g_gptr[GG] = NN;
        else {
            int lo = 0, hi = NN;
            while (lo < hi) {
                int mid = (lo + hi) >> 1;
                if (batch[mid] < i) lo = mid + 1; else hi = mid;
            }
            g_gptr[i] = lo;
        }
    }
}

// Degree count: 4 edges per thread -> 4 independent RED chains (MLP=4).
__global__ void deg_kernel(const int* __restrict__ ei) {
    int base = blockIdx.x * 1024 + threadIdx.x;
    #pragma unroll
    for (int k = 0; k < 4; k++) {
        int e = base + k * 256;
        if (e < EE) atomicAdd(&g_deg[ei[EE + e]], 1);
    }
}

// Exclusive prefix sum of g_deg -> g_ptr, g_cursor. Single block, 1024 threads.
__global__ void scan_kernel() {
    const int IT = 49;  // 1024*49 = 50176 >= NN
    int t = threadIdx.x;
    int base = t * IT;
    int sum = 0;
    for (int k = 0; k < IT; k++) {
        int i = base + k;
        if (i < NN) sum += g_deg[i];
    }
    int incl = sum;
    #pragma unroll
    for (int o = 1; o < 32; o <<= 1) {
        int u = __shfl_up_sync(0xffffffffu, incl, o);
        if ((t & 31) >= o) incl += u;
    }
    __shared__ int ws[32];
    if ((t & 31) == 31) ws[t >> 5] = incl;
    __syncthreads();
    if (t < 32) {
        int wv = ws[t];
        int wincl = wv;
        #pragma unroll
        for (int o = 1; o < 32; o <<= 1) {
            int u = __shfl_up_sync(0xffffffffu, wincl, o);
            if (t >= o) wincl += u;
        }
        ws[t] = wincl - wv;  // exclusive warp offset
    }
    __syncthreads();
    int run = ws[t >> 5] + (incl - sum);
    for (int k = 0; k < IT; k++) {
        int i = base + k;
        if (i < NN) {
            g_ptr[i] = run;
            g_cursor[i] = run;
            run += g_deg[i];
        }
    }
    if (t == 0) g_ptr[NN] = EE;
}

// CSR scatter: 4 edges per thread -> 4 independent atomic+store chains.
__global__ void scatter_kernel(const int* __restrict__ ei) {
    int base = blockIdx.x * 1024 + threadIdx.x;
    #pragma unroll
    for (int k = 0; k < 4; k++) {
        int e = base + k * 256;
        if (e < EE) {
            int s = ei[e];
            int d = ei[EE + e];
            int pos = atomicAdd(&g_cursor[d], 1);
            g_src[pos] = s;
            g_eid[pos] = e;
        }
    }
}

// xw1 = x @ W1, plus per-node attention scalars als1/ald1. 16 nodes per 256-thread block.
__global__ __launch_bounds__(256) void gemm1_kernel(const float* __restrict__ x,
                             const float* __restrict__ W1,
                             const float* __restrict__ as1, const float* __restrict__ ad1) {
    __shared__ float xs[16][FIN];
    int n0 = blockIdx.x * 16;
    for (int idx = threadIdx.x; idx < 16 * FIN; idx += 256)
        xs[idx >> 7][idx & 127] = x[(size_t)(n0 + (idx >> 7)) * FIN + (idx & 127)];
    __syncthreads();
    int jg = threadIdx.x & 15;   // float4 column group (4 of 64 outputs)
    int nd = threadIdx.x >> 4;   // node within block
    const float4* W1v = (const float4*)W1;
    float4 acc = make_float4(0.f, 0.f, 0.f, 0.f);
    #pragma unroll 4
    for (int k = 0; k < FIN; k++) {
        float xv = xs[nd][k];
        float4 w = W1v[k * 16 + jg];
        acc.x += xv * w.x; acc.y += xv * w.y; acc.z += xv * w.z; acc.w += xv * w.w;
    }
    int n = n0 + nd;
    ((float4*)g_xw1)[n * 16 + jg] = acc;
    float4 a_s = ((const float4*)as1)[jg];
    float4 a_d = ((const float4*)ad1)[jg];
    float ps = acc.x * a_s.x + acc.y * a_s.y + acc.z * a_s.z + acc.w * a_s.w;
    float pd = acc.x * a_d.x + acc.y * a_d.y + acc.z * a_d.z + acc.w * a_d.w;
    ps += __shfl_xor_sync(0xffffffffu, ps, 1);
    pd += __shfl_xor_sync(0xffffffffu, pd, 1);
    if ((threadIdx.x & 1) == 0) {
        int h = jg >> 1;
        g_als1[n * 8 + h] = ps;
        g_ald1[n * 8 + h] = pd;
    }
}

// Per-CSR-slot edge attention logits from edge_attr (one read of edge_attr, ever).
__global__ void alE_kernel(const float* __restrict__ ea) {
    __shared__ float sM1[ED * 8];
    __shared__ float sm2[ED];
    if (threadIdx.x < 128) sM1[threadIdx.x] = g_M1[threadIdx.x];
    if (threadIdx.x < ED) sm2[threadIdx.x] = g_m2[threadIdx.x];
    __syncthreads();
    int j = blockIdx.x * blockDim.x + threadIdx.x;
    if (j >= EE) return;
    int e = g_eid[j];
    const float4* p = (const float4*)(ea + (size_t)e * ED);
    float4 q0 = p[0], q1 = p[1], q2 = p[2], q3 = p[3];
    float av[16] = {q0.x, q0.y, q0.z, q0.w, q1.x, q1.y, q1.z, q1.w,
                    q2.x, q2.y, q2.z, q2.w, q3.x, q3.y, q3.z, q3.w};
    float r[8] = {0, 0, 0, 0, 0, 0, 0, 0};
    float r2 = 0.f;
    #pragma unroll
    for (int d = 0; d < ED; d++) {
        float a = av[d];
        #pragma unroll
        for (int h = 0; h < 8; h++) r[h] += a * sM1[d * 8 + h];
        r2 += a * sm2[d];
    }
    float4* o = (float4*)(g_alE1 + (size_t)j * 8);
    o[0] = make_float4(r[0], r[1], r[2], r[3]);
    o[1] = make_float4(r[4], r[5], r[6], r[7]);
    g_alE2[j] = r2;
}

// Layer-1 softmax + aggregation + ELU, FUSED with gemm2 (xw2 = h@W2) and the
// self-loop fold (alE_self = mean of incoming alE, accumulated for free in-loop).
// One warp per node; block stages 8 nodes' h rows in smem for the gemm2 phase.
__global__ __launch_bounds__(256) void agg1_kernel(const float* __restrict__ b1,
        const float* __restrict__ W2,
        const float* __restrict__ as2, const float* __restrict__ ad2) {
    __shared__ float hs[8][HID];
    int warp = threadIdx.x >> 5;
    int n = blockIdx.x * 8 + warp;           // NN % 8 == 0
    int l = threadIdx.x & 31;
    int h8 = l & 7;
    int h0 = l >> 3;
    int h1 = h0 + 4;
    const float* __restrict__ als1 = g_als1;
    const float* __restrict__ alE1 = g_alE1;
    const float* __restrict__ xw1  = g_xw1;
    const int*   __restrict__ srcv = g_src;

    float ald   = g_ald1[n * 8 + h8];
    float myals = als1[n * 8 + h8];
    int beg = g_ptr[n], end = g_ptr[n + 1];

    float s = 0.f, salE = 0.f;
    float acc0 = 0.f, acc1 = 0.f;
    int j = beg;
    // unroll-by-2: 8 independent gathers issued before any consumption
    for (; j + 1 < end; j += 2) {
        int sA = srcv[j], sB = srcv[j + 1];
        float alsA = als1[sA * 8 + h8];
        float alsB = als1[sB * 8 + h8];
        float aleA = alE1[(size_t)j * 8 + h8];
        float aleB = alE1[(size_t)(j + 1) * 8 + h8];
        float xa0 = xw1[(size_t)sA * 64 + l];
        float xa1 = xw1[(size_t)sA * 64 + 32 + l];
        float xb0 = xw1[(size_t)sB * 64 + l];
        float xb1 = xw1[(size_t)sB * 64 + 32 + l];
        salE += aleA + aleB;
        float zA = alsA + ald + aleA; zA = zA > 0.f ? zA : NEG * zA;
        float zB = alsB + ald + aleB; zB = zB > 0.f ? zB : NEG * zB;
        float eA = __expf(zA), eB = __expf(zB);
        s += eA + eB;
        float wA0 = __shfl_sync(0xffffffffu, eA, h0);
        float wA1 = __shfl_sync(0xffffffffu, eA, h1);
        float wB0 = __shfl_sync(0xffffffffu, eB, h0);
        float wB1 = __shfl_sync(0xffffffffu, eB, h1);
        acc0 += xa0 * wA0; acc0 += xb0 * wB0;
        acc1 += xa1 * wA1; acc1 += xb1 * wB1;
    }
    if (j < end) {
        int sA = srcv[j];
        float alsA = als1[sA * 8 + h8];
        float aleA = alE1[(size_t)j * 8 + h8];
        float xa0 = xw1[(size_t)sA * 64 + l];
        float xa1 = xw1[(size_t)sA * 64 + 32 + l];
        salE += aleA;
        float zA = alsA + ald + aleA; zA = zA > 0.f ? zA : NEG * zA;
        float eA = __expf(zA);
        s += eA;
        float wA0 = __shfl_sync(0xffffffffu, eA, h0);
        float wA1 = __shfl_sync(0xffffffffu, eA, h1);
        acc0 += xa0 * wA0;
        acc1 += xa1 * wA1;
    }
    // self loop: alE_self = (sum of incoming alE)/max(deg,1) -- salE is already full per-head sum
    float rd = 1.f / (float)max(end - beg, 1);
    float zs = myals + ald + salE * rd;
    zs = zs > 0.f ? zs : NEG * zs;
    float es = __expf(zs);
    s += es;
    float ws0 = __shfl_sync(0xffffffffu, es, h0);
    float ws1 = __shfl_sync(0xffffffffu, es, h1);
    acc0 += xw1[(size_t)n * 64 + l] * ws0;
    acc1 += xw1[(size_t)n * 64 + 32 + l] * ws1;
    // s is already the full per-head denominator (every lane walked every edge)
    float s0 = __shfl_sync(0xffffffffu, s, h0);
    float s1 = __shfl_sync(0xffffffffu, s, h1);
    float o0 = acc0 / (s0 + 1e-16f) + b1[l];
    float o1 = acc1 / (s1 + 1e-16f) + b1[32 + l];
    o0 = o0 > 0.f ? o0 : (__expf(o0) - 1.f);   // ELU
    o1 = o1 > 0.f ? o1 : (__expf(o1) - 1.f);
    hs[warp][l] = o0;
    hs[warp][32 + l] = o1;
    __syncthreads();

    // ---- fused gemm2: xw2[n] = h[n] @ W2, plus als2/ald2 scalars ----
    const float4* W2v = (const float4*)W2;
    float4 acc = make_float4(0.f, 0.f, 0.f, 0.f);
    #pragma unroll 8
    for (int k = 0; k < HID; k++) {
        float hv = hs[warp][k];
        float4 w = W2v[k * 32 + l];
        acc.x += hv * w.x; acc.y += hv * w.y; acc.z += hv * w.z; acc.w += hv * w.w;
    }
    ((float4*)g_xw2)[(size_t)n * 32 + l] = acc;
    float4 a_s = ((const float4*)as2)[l];
    float4 a_d = ((const float4*)ad2)[l];
    float ps = acc.x * a_s.x + acc.y * a_s.y + acc.z * a_s.z + acc.w * a_s.w;
    float pd = acc.x * a_d.x + acc.y * a_d.y + acc.z * a_d.z + acc.w * a_d.w;
    #pragma unroll
    for (int o = 16; o > 0; o >>= 1) {
        ps += __shfl_xor_sync(0xffffffffu, ps, o);
        pd += __shfl_xor_sync(0xffffffffu, pd, o);
    }
    if (l == 0) {
        g_als2[n] = ps;
        g_ald2[n] = pd;
    }
}

// Layer-2 softmax + aggregation with fused self-loop; one warp per node,
// lane owns 4 features; unroll-by-2 for MLP.
__global__ __launch_bounds__(256) void agg2_kernel(const float* __restrict__ b2) {
    int warp = (blockIdx.x * blockDim.x + threadIdx.x) >> 5;
    if (warp >= NN) return;
    int n = warp;
    int l = threadIdx.x & 31;
    const float4* __restrict__ xw  = (const float4*)g_xw2;
    const float*  __restrict__ als2 = g_als2;
    const float*  __restrict__ alE2 = g_alE2;
    const int*    __restrict__ srcv = g_src;
    float ald   = g_ald2[n];
    float myals = als2[n];
    int beg = g_ptr[n], end = g_ptr[n + 1];
    float s = 0.f, salE = 0.f;
    float4 acc = make_float4(0.f, 0.f, 0.f, 0.f);
    int j = beg;
    for (; j + 1 < end; j += 2) {
        int sA = srcv[j], sB = srcv[j + 1];
        float aleA = alE2[j], aleB = alE2[j + 1];
        float alsA = als2[sA], alsB = als2[sB];
        float4 uA = xw[(size_t)sA * 32 + l];
        float4 uB = xw[(size_t)sB * 32 + l];
        salE += aleA + aleB;
        float zA = alsA + ald + aleA; zA = zA > 0.f ? zA : NEG * zA;
        float zB = alsB + ald + aleB; zB = zB > 0.f ? zB : NEG * zB;
        float eA = __expf(zA), eB = __expf(zB);
        s += eA + eB;
        acc.x += uA.x * eA; acc.y += uA.y * eA; acc.z += uA.z * eA; acc.w += uA.w * eA;
        acc.x += uB.x * eB; acc.y += uB.y * eB; acc.z += uB.z * eB; acc.w += uB.w * eB;
    }
    if (j < end) {
        int sA = srcv[j];
        float aleA = alE2[j];
        float alsA = als2[sA];
        float4 uA = xw[(size_t)sA * 32 + l];
        salE += aleA;
        float zA = alsA + ald + aleA; zA = zA > 0.f ? zA : NEG * zA;
        float eA = __expf(zA);
        s += eA;
        acc.x += uA.x * eA; acc.y += uA.y * eA; acc.z += uA.z * eA; acc.w += uA.w * eA;
    }
    // self loop
    float rd = 1.f / (float)max(end - beg, 1);
    float zs = myals + ald + salE * rd;
    zs = zs > 0.f ? zs : NEG * zs;
    float es = __expf(zs);
    s += es;
    float4 v = xw[(size_t)n * 32 + l];
    acc.x += v.x * es; acc.y += v.y * es; acc.z += v.z * es; acc.w += v.w * es;

    float inv = 1.f / (s + 1e-16f);
    float4 bb = ((const float4*)b2)[l];
    float4 o = make_float4(acc.x * inv + bb.x, acc.y * inv + bb.y,
                           acc.z * inv + bb.z, acc.w * inv + bb.w);
    ((float4*)g_out2)[(size_t)n * 32 + l] = o;
}

// Global mean pool: one block per graph; 256 threads = 2-way row split per feature.
__global__ void pool_kernel(float* __restrict__ out) {
    __shared__ float sm[128];
    int g = blockIdx.x;
    int f = threadIdx.x & 127;
    int part = threadIdx.x >> 7;
    int s = g_gptr[g], e = g_gptr[g + 1];
    float acc = 0.f;
    for (int n = s + part; n < e; n += 2) acc += g_out2[(size_t)n * OUT + f];
    if (part == 1) sm[f] = acc;
    __syncthreads();
    if (part == 0)
        out[g * OUT + f] = (acc + sm[f]) / fmaxf((float)(e - s), 1.f);
}

// ---------------- launch ----------------
extern "C" void kernel_launch(void* const* d_in, const int* in_sizes, int n_in,
                              void* d_out, int out_size) {
    const float* x     = (const float*)d_in[0];
    const int*   ei    = (const int*)d_in[1];
    const float* ea    = (const float*)d_in[2];
    const int*   batch = (const int*)d_in[3];
    const float* W1    = (const float*)d_in[4];
    const float* as1   = (const float*)d_in[5];
    const float* ad1   = (const float*)d_in[6];
    const float* ae1   = (const float*)d_in[7];
    const float* We1   = (const float*)d_in[8];
    const float* b1    = (const float*)d_in[9];
    const float* W2    = (const float*)d_in[10];
    const float* as2   = (const float*)d_in[11];
    const float* ad2   = (const float*)d_in[12];
    const float* ae2   = (const float*)d_in[13];
    const float* We2   = (const float*)d_in[14];
    const float* b2    = (const float*)d_in[15];
    float* out = (float*)d_out;

    setup_kernel<<<(NN + 255) / 256, 256>>>(We1, ae1, We2, ae2, batch);
    deg_kernel<<<(EE + 1023) / 1024, 256>>>(ei);
    scan_kernel<<<1, 1024>>>();
    scatter_kernel<<<(EE + 1023) / 1024, 256>>>(ei);
    gemm1_kernel<<<NN / 16, 256>>>(x, W1, as1, ad1);
    alE_kernel<<<(EE + 255) / 256, 256>>>(ea);
    agg1_kernel<<<NN / 8, 256>>>(b1, W2, as2, ad2);
    agg2_kernel<<<NN / 8, 256>>>(b2);
    pool_kernel<<<GG, 256>>>(out);
}

// round 6
// speedup vs baseline: 1.3599x; 1.2399x over previous
#include <cuda_runtime.h>
#include <cuda_bf16.h>
#include <math.h>

// Problem constants (fixed by the reference)
#define NN 50000
#define EE 800000
#define FIN 128
#define ED 16
#define HID 64
#define OUT 128
#define GG 256
#define NEG 0.2f
#define NPAD 53248   // 1024*52, scan padding

// ---------------- device scratch (static, allocation-free) ----------------
__device__ int   g_deg[NPAD];
__device__ int   g_ptr[NN + 4];
__device__ int   g_cursor[NN];
__device__ int   g_srcCSR[EE];
__device__ float g_alE1[EE * 8];     // per CSR slot, 8 heads (edge-only logit, layer1)
__device__ float g_alE2[EE];         // per CSR slot (edge-only logit, layer2)
__device__ __nv_bfloat162 g_xw1b[NN * 32];   // xw1 values, bf16 (64 feats/node)
__device__ float g_als1[NN * 8];
__device__ float g_ald1[NN * 8];
__device__ __nv_bfloat162 g_xw2b[NN * 64];   // xw2 values, bf16 (128 feats/node)
__device__ float g_als2[NN];
__device__ float g_ald2[NN];
__device__ float g_out2[NN * OUT];
__device__ float g_M1[ED * 8];
__device__ float g_m2[ED];
__device__ int   g_gptr[GG + 1];

// ---------------- kernels ----------------

// Fused setup: zero padded deg + reduced attention matrices + graph offsets.
__global__ void setup_kernel(const float* __restrict__ We1, const float* __restrict__ ae1,
                             const float* __restrict__ We2, const float* __restrict__ ae2,
                             const int* __restrict__ batch) {
    int i = blockIdx.x * blockDim.x + threadIdx.x;
    if (i < NPAD) g_deg[i] = 0;
    if (i < 128) {
        int d = i >> 3, h = i & 7;
        float s = 0.f;
        #pragma unroll
        for (int c = 0; c < 8; c++) s += We1[d * 64 + h * 8 + c] * ae1[h * 8 + c];
        g_M1[d * 8 + h] = s;
    }
    if (i < ED) {
        float s = 0.f;
        for (int c = 0; c < OUT; c++) s += We2[i * OUT + c] * ae2[c];
        g_m2[i] = s;
    }
    if (i <= GG) {
        if (i == GG) g_gptr[GG] = NN;
        else {
            int lo = 0, hi = NN;
            while (lo < hi) {
                int mid = (lo + hi) >> 1;
                if (batch[mid] < i) lo = mid + 1; else hi = mid;
            }
            g_gptr[i] = lo;
        }
    }
}

// Degree count: int4 dst load, 4 independent RED chains per thread.
__global__ void deg_kernel(const int* __restrict__ ei) {
    int e4 = blockIdx.x * blockDim.x + threadIdx.x;
    if (e4 < EE / 4) {
        int4 d = ((const int4*)(ei + EE))[e4];
        atomicAdd(&g_deg[d.x], 1);
        atomicAdd(&g_deg[d.y], 1);
        atomicAdd(&g_deg[d.z], 1);
        atomicAdd(&g_deg[d.w], 1);
    }
}

// Exclusive prefix sum of g_deg -> g_ptr, g_cursor. Single block, 1024 threads, int4.
__global__ void scan_kernel() {
    int t = threadIdx.x;
    const int4* dv = (const int4*)g_deg;
    int b4 = t * 13;            // 13 int4 = 52 ints per thread
    int sum = 0;
    #pragma unroll
    for (int k = 0; k < 13; k++) {
        int4 q = dv[b4 + k];
        sum += q.x + q.y + q.z + q.w;
    }
    int incl = sum;
    #pragma unroll
    for (int o = 1; o < 32; o <<= 1) {
        int u = __shfl_up_sync(0xffffffffu, incl, o);
        if ((t & 31) >= o) incl += u;
    }
    __shared__ int ws[32];
    if ((t & 31) == 31) ws[t >> 5] = incl;
    __syncthreads();
    if (t < 32) {
        int wv = ws[t];
        int wincl = wv;
        #pragma unroll
        for (int o = 1; o < 32; o <<= 1) {
            int u = __shfl_up_sync(0xffffffffu, wincl, o);
            if (t >= o) wincl += u;
        }
        ws[t] = wincl - wv;
    }
    __syncthreads();
    int run = ws[t >> 5] + (incl - sum);
    #pragma unroll
    for (int k = 0; k < 13; k++) {
        int4 q = dv[b4 + k];
        int i = t * 52 + k * 4;
        int4 p;
        p.x = run; p.y = run + q.x; p.z = p.y + q.y; p.w = p.z + q.z;
        run = p.w + q.w;
        if (i < NN) {                     // NN%4==0 so whole int4 in range
            ((int4*)g_ptr)[i >> 2] = p;
            ((int4*)g_cursor)[i >> 2] = p;
        }
    }
    if (t == 0) g_ptr[NN] = EE;
}

// Fused CSR scatter + edge-logit compute. Per thread: 4 edges.
// ea is read COALESCED in original edge order; logits scatter-written to CSR slots.
__global__ __launch_bounds__(256) void scatter_kernel(const int* __restrict__ ei,
                                                      const float* __restrict__ ea) {
    __shared__ float sM1[ED * 8];
    __shared__ float sm2[ED];
    if (threadIdx.x < 128) sM1[threadIdx.x] = g_M1[threadIdx.x];
    if (threadIdx.x < ED) sm2[threadIdx.x] = g_m2[threadIdx.x];
    __syncthreads();
    int e4 = blockIdx.x * blockDim.x + threadIdx.x;
    if (e4 >= EE / 4) return;
    int4 s4 = ((const int4*)ei)[e4];
    int4 d4 = ((const int4*)(ei + EE))[e4];
    int srcs[4] = {s4.x, s4.y, s4.z, s4.w};
    int dsts[4] = {d4.x, d4.y, d4.z, d4.w};
    int pos[4];
    #pragma unroll
    for (int k = 0; k < 4; k++)
        pos[k] = atomicAdd(&g_cursor[dsts[k]], 1);   // 4 overlapping ATOMG chains
    #pragma unroll
    for (int k = 0; k < 4; k++) {
        int e = e4 * 4 + k;
        const float4* p = (const float4*)(ea + (size_t)e * ED);
        float4 q0 = p[0], q1 = p[1], q2 = p[2], q3 = p[3];
        float av[16] = {q0.x, q0.y, q0.z, q0.w, q1.x, q1.y, q1.z, q1.w,
                        q2.x, q2.y, q2.z, q2.w, q3.x, q3.y, q3.z, q3.w};
        float r[8] = {0, 0, 0, 0, 0, 0, 0, 0};
        float r2 = 0.f;
        #pragma unroll
        for (int d = 0; d < ED; d++) {
            float a = av[d];
            #pragma unroll
            for (int h = 0; h < 8; h++) r[h] += a * sM1[d * 8 + h];
            r2 += a * sm2[d];
        }
        int pk = pos[k];
        g_srcCSR[pk] = srcs[k];
        float4* o = (float4*)(g_alE1 + (size_t)pk * 8);
        o[0] = make_float4(r[0], r[1], r[2], r[3]);
        o[1] = make_float4(r[4], r[5], r[6], r[7]);
        g_alE2[pk] = r2;
    }
}

// xw1 = x @ W1 (bf16 out), plus per-node attention scalars als1/ald1 (fp32).
__global__ __launch_bounds__(256) void gemm1_kernel(const float* __restrict__ x,
                             const float* __restrict__ W1,
                             const float* __restrict__ as1, const float* __restrict__ ad1) {
    __shared__ float xs[16][FIN];
    int n0 = blockIdx.x * 16;
    for (int idx = threadIdx.x; idx < 16 * FIN; idx += 256)
        xs[idx >> 7][idx & 127] = x[(size_t)(n0 + (idx >> 7)) * FIN + (idx & 127)];
    __syncthreads();
    int jg = threadIdx.x & 15;   // float4 column group (4 of 64 outputs)
    int nd = threadIdx.x >> 4;   // node within block
    const float4* W1v = (const float4*)W1;
    float4 acc = make_float4(0.f, 0.f, 0.f, 0.f);
    #pragma unroll 4
    for (int k = 0; k < FIN; k++) {
        float xv = xs[nd][k];
        float4 w = W1v[k * 16 + jg];
        acc.x += xv * w.x; acc.y += xv * w.y; acc.z += xv * w.z; acc.w += xv * w.w;
    }
    int n = n0 + nd;
    __nv_bfloat162 b0 = __float22bfloat162_rn(make_float2(acc.x, acc.y));
    __nv_bfloat162 b1v = __float22bfloat162_rn(make_float2(acc.z, acc.w));
    uint2 pk;
    pk.x = *(unsigned int*)&b0;
    pk.y = *(unsigned int*)&b1v;
    ((uint2*)(g_xw1b + (size_t)n * 32))[jg] = pk;
    float4 a_s = ((const float4*)as1)[jg];
    float4 a_d = ((const float4*)ad1)[jg];
    float ps = acc.x * a_s.x + acc.y * a_s.y + acc.z * a_s.z + acc.w * a_s.w;
    float pd = acc.x * a_d.x + acc.y * a_d.y + acc.z * a_d.z + acc.w * a_d.w;
    ps += __shfl_xor_sync(0xffffffffu, ps, 1);
    pd += __shfl_xor_sync(0xffffffffu, pd, 1);
    if ((threadIdx.x & 1) == 0) {
        int h = jg >> 1;
        g_als1[n * 8 + h] = ps;
        g_ald1[n * 8 + h] = pd;
    }
}

// Layer-1 softmax + aggregation + ELU, fused with gemm2 and self-loop fold.
// One warp per node. Lane l: computes logits for head l&7; owns features 2l,2l+1
// (value head l>>2, one bf16x2 load per edge).
__global__ __launch_bounds__(256) void agg1_kernel(const float* __restrict__ b1,
        const float* __restrict__ W2,
        const float* __restrict__ as2, const float* __restrict__ ad2) {
    __shared__ float hs[8][HID];
    int warp = threadIdx.x >> 5;
    int n = blockIdx.x * 8 + warp;           // NN % 8 == 0
    int l = threadIdx.x & 31;
    int h8 = l & 7;
    int hv = l >> 2;                          // value head for features 2l,2l+1
    const float* __restrict__ als1 = g_als1;
    const float* __restrict__ alE1 = g_alE1;
    const __nv_bfloat162* __restrict__ xw1b = g_xw1b;
    const int* __restrict__ srcv = g_srcCSR;

    float ald   = g_ald1[n * 8 + h8];
    float myals = als1[n * 8 + h8];
    int beg = g_ptr[n], end = g_ptr[n + 1];

    float s = 0.f, salE = 0.f;
    float acc0 = 0.f, acc1 = 0.f;
    int j = beg;
    for (; j + 1 < end; j += 2) {
        int sA = srcv[j], sB = srcv[j + 1];
        float alsA = als1[sA * 8 + h8];
        float alsB = als1[sB * 8 + h8];
        float aleA = alE1[(size_t)j * 8 + h8];
        float aleB = alE1[(size_t)(j + 1) * 8 + h8];
        __nv_bfloat162 vA = xw1b[(size_t)sA * 32 + l];
        __nv_bfloat162 vB = xw1b[(size_t)sB * 32 + l];
        salE += aleA + aleB;
        float zA = alsA + ald + aleA; zA = zA > 0.f ? zA : NEG * zA;
        float zB = alsB + ald + aleB; zB = zB > 0.f ? zB : NEG * zB;
        float eA = __expf(zA), eB = __expf(zB);
        s += eA + eB;
        float wA = __shfl_sync(0xffffffffu, eA, hv);
        float wB = __shfl_sync(0xffffffffu, eB, hv);
        float2 fA = __bfloat1622float2(vA);
        float2 fB = __bfloat1622float2(vB);
        acc0 += fA.x * wA; acc1 += fA.y * wA;
        acc0 += fB.x * wB; acc1 += fB.y * wB;
    }
    if (j < end) {
        int sA = srcv[j];
        float alsA = als1[sA * 8 + h8];
        float aleA = alE1[(size_t)j * 8 + h8];
        __nv_bfloat162 vA = xw1b[(size_t)sA * 32 + l];
        salE += aleA;
        float zA = alsA + ald + aleA; zA = zA > 0.f ? zA : NEG * zA;
        float eA = __expf(zA);
        s += eA;
        float wA = __shfl_sync(0xffffffffu, eA, hv);
        float2 fA = __bfloat1622float2(vA);
        acc0 += fA.x * wA; acc1 += fA.y * wA;
    }
    // self loop: edge logit = mean of incoming edge logits (salE is full per-head sum)
    float rd = 1.f / (float)max(end - beg, 1);
    float zs = myals + ald + salE * rd;
    zs = zs > 0.f ? zs : NEG * zs;
    float es = __expf(zs);
    s += es;
    float wsv = __shfl_sync(0xffffffffu, es, hv);
    float2 fS = __bfloat1622float2(xw1b[(size_t)n * 32 + l]);
    acc0 += fS.x * wsv; acc1 += fS.y * wsv;
    // s is already the full per-head denominator
    float sv = __shfl_sync(0xffffffffu, s, hv);
    float2 bb = ((const float2*)b1)[l];
    float o0 = acc0 / (sv + 1e-16f) + bb.x;
    float o1 = acc1 / (sv + 1e-16f) + bb.y;
    o0 = o0 > 0.f ? o0 : (__expf(o0) - 1.f);   // ELU
    o1 = o1 > 0.f ? o1 : (__expf(o1) - 1.f);
    hs[warp][2 * l] = o0;
    hs[warp][2 * l + 1] = o1;
    __syncthreads();

    // ---- fused gemm2: xw2[n] = h[n] @ W2 (bf16 out), plus als2/ald2 scalars ----
    const float4* W2v = (const float4*)W2;
    float4 acc = make_float4(0.f, 0.f, 0.f, 0.f);
    #pragma unroll 8
    for (int k = 0; k < HID; k++) {
        float hv2 = hs[warp][k];
        float4 w = W2v[k * 32 + l];
        acc.x += hv2 * w.x; acc.y += hv2 * w.y; acc.z += hv2 * w.z; acc.w += hv2 * w.w;
    }
    __nv_bfloat162 c0 = __float22bfloat162_rn(make_float2(acc.x, acc.y));
    __nv_bfloat162 c1 = __float22bfloat162_rn(make_float2(acc.z, acc.w));
    uint2 pk;
    pk.x = *(unsigned int*)&c0;
    pk.y = *(unsigned int*)&c1;
    ((uint2*)(g_xw2b + (size_t)n * 64))[l] = pk;
    float4 a_s = ((const float4*)as2)[l];
    float4 a_d = ((const float4*)ad2)[l];
    float ps = acc.x * a_s.x + acc.y * a_s.y + acc.z * a_s.z + acc.w * a_s.w;
    float pd = acc.x * a_d.x + acc.y * a_d.y + acc.z * a_d.z + acc.w * a_d.w;
    #pragma unroll
    for (int o = 16; o > 0; o >>= 1) {
        ps += __shfl_xor_sync(0xffffffffu, ps, o);
        pd += __shfl_xor_sync(0xffffffffu, pd, o);
    }
    if (l == 0) {
        g_als2[n] = ps;
        g_ald2[n] = pd;
    }
}

// Layer-2 softmax + aggregation with fused self-loop; one warp per node,
// lane owns features 4l..4l+3 via one 8B bf16 load per edge.
__global__ __launch_bounds__(256) void agg2_kernel(const float* __restrict__ b2) {
    int warp = (blockIdx.x * blockDim.x + threadIdx.x) >> 5;
    if (warp >= NN) return;
    int n = warp;
    int l = threadIdx.x & 31;
    const uint2* __restrict__ xw = (const uint2*)g_xw2b;
    const float* __restrict__ als2 = g_als2;
    const float* __restrict__ alE2 = g_alE2;
    const int*   __restrict__ srcv = g_srcCSR;
    float ald   = g_ald2[n];
    float myals = als2[n];
    int beg = g_ptr[n], end = g_ptr[n + 1];
    float s = 0.f, salE = 0.f;
    float4 acc = make_float4(0.f, 0.f, 0.f, 0.f);
    int j = beg;
    for (; j + 1 < end; j += 2) {
        int sA = srcv[j], sB = srcv[j + 1];
        float aleA = alE2[j], aleB = alE2[j + 1];
        float alsA = als2[sA], alsB = als2[sB];
        uint2 uA = xw[(size_t)sA * 32 + l];
        uint2 uB = xw[(size_t)sB * 32 + l];
        salE += aleA + aleB;
        float zA = alsA + ald + aleA; zA = zA > 0.f ? zA : NEG * zA;
        float zB = alsB + ald + aleB; zB = zB > 0.f ? zB : NEG * zB;
        float eA = __expf(zA), eB = __expf(zB);
        s += eA + eB;
        float2 fA0 = __bfloat1622float2(*(__nv_bfloat162*)&uA.x);
        float2 fA1 = __bfloat1622float2(*(__nv_bfloat162*)&uA.y);
        float2 fB0 = __bfloat1622float2(*(__nv_bfloat162*)&uB.x);
        float2 fB1 = __bfloat1622float2(*(__nv_bfloat162*)&uB.y);
        acc.x += fA0.x * eA; acc.y += fA0.y * eA; acc.z += fA1.x * eA; acc.w += fA1.y * eA;
        acc.x += fB0.x * eB; acc.y += fB0.y * eB; acc.z += fB1.x * eB; acc.w += fB1.y * eB;
    }
    if (j < end) {
        int sA = srcv[j];
        float aleA = alE2[j];
        float alsA = als2[sA];
        uint2 uA = xw[(size_t)sA * 32 + l];
        salE += aleA;
        float zA = alsA + ald + aleA; zA = zA > 0.f ? zA : NEG * zA;
        float eA = __expf(zA);
        s += eA;
        float2 fA0 = __bfloat1622float2(*(__nv_bfloat162*)&uA.x);
        float2 fA1 = __bfloat1622float2(*(__nv_bfloat162*)&uA.y);
        acc.x += fA0.x * eA; acc.y += fA0.y * eA; acc.z += fA1.x * eA; acc.w += fA1.y * eA;
    }
    // self loop
    float rd = 1.f / (float)max(end - beg, 1);
    float zs = myals + ald + salE * rd;
    zs = zs > 0.f ? zs : NEG * zs;
    float es = __expf(zs);
    s += es;
    uint2 uS = xw[(size_t)n * 32 + l];
    float2 fS0 = __bfloat1622float2(*(__nv_bfloat162*)&uS.x);
    float2 fS1 = __bfloat1622float2(*(__nv_bfloat162*)&uS.y);
    acc.x += fS0.x * es; acc.y += fS0.y * es; acc.z += fS1.x * es; acc.w += fS1.y * es;

    float inv = 1.f / (s + 1e-16f);
    float4 bb = ((const float4*)b2)[l];
    float4 o = make_float4(acc.x * inv + bb.x, acc.y * inv + bb.y,
                           acc.z * inv + bb.z, acc.w * inv + bb.w);
    ((float4*)g_out2)[(size_t)n * 32 + l] = o;
}

// Global mean pool: one block per graph; 512 threads = 4-way row split per feature.
__global__ void pool_kernel(float* __restrict__ out) {
    __shared__ float sm[4][128];
    int g = blockIdx.x;
    int f = threadIdx.x & 127;
    int part = threadIdx.x >> 7;
    int s = g_gptr[g], e = g_gptr[g + 1];
    float acc = 0.f;
    for (int n = s + part; n < e; n += 4) acc += g_out2[(size_t)n * OUT + f];
    sm[part][f] = acc;
    __syncthreads();
    if (part == 0)
        out[g * OUT + f] = (sm[0][f] + sm[1][f] + sm[2][f] + sm[3][f])
                           / fmaxf((float)(e - s), 1.f);
}

// ---------------- launch ----------------
extern "C" void kernel_launch(void* const* d_in, const int* in_sizes, int n_in,
                              void* d_out, int out_size) {
    const float* x     = (const float*)d_in[0];
    const int*   ei    = (const int*)d_in[1];
    const float* ea    = (const float*)d_in[2];
    const int*   batch = (const int*)d_in[3];
    const float* W1    = (const float*)d_in[4];
    const float* as1   = (const float*)d_in[5];
    const float* ad1   = (const float*)d_in[6];
    const float* ae1   = (const float*)d_in[7];
    const float* We1   = (const float*)d_in[8];
    const float* b1    = (const float*)d_in[9];
    const float* W2    = (const float*)d_in[10];
    const float* as2   = (const float*)d_in[11];
    const float* ad2   = (const float*)d_in[12];
    const float* ae2   = (const float*)d_in[13];
    const float* We2   = (const float*)d_in[14];
    const float* b2    = (const float*)d_in[15];
    float* out = (float*)d_out;

    setup_kernel<<<NPAD / 256, 256>>>(We1, ae1, We2, ae2, batch);
    deg_kernel<<<(EE / 4 + 255) / 256, 256>>>(ei);
    scan_kernel<<<1, 1024>>>();
    gemm1_kernel<<<NN / 16, 256>>>(x, W1, as1, ad1);
    scatter_kernel<<<(EE / 4 + 255) / 256, 256>>>(ei, ea);
    agg1_kernel<<<NN / 8, 256>>>(b1, W2, as2, ad2);
    agg2_kernel<<<NN / 8, 256>>>(b2);
    pool_kernel<<<GG, 512>>>(out);
}

// round 7
// speedup vs baseline: 1.4642x; 1.0767x over previous
#include <cuda_runtime.h>
#include <cuda_bf16.h>
#include <math.h>

// Problem constants (fixed by the reference)
#define NN 50000
#define EE 800000
#define FIN 128
#define ED 16
#define HID 64
#define OUT 128
#define GG 256
#define NEG 0.2f
#define NPAD 53248   // 1024*52, scan padding

// ---------------- device scratch (static, allocation-free) ----------------
__device__ int   g_deg[NPAD];
__device__ int   g_ptr[NN + 4];
__device__ int   g_cursor[NN];
__device__ int   g_srcCSR[EE];
__device__ float g_alE1[EE * 8];     // per CSR slot, 8 heads (edge-only logit, layer1)
__device__ float g_alE2[EE];         // per CSR slot (edge-only logit, layer2)
__device__ __nv_bfloat162 g_xw1b[NN * 32];   // xw1 values, bf16 (64 feats/node)
__device__ float g_als1[NN * 8];
__device__ float g_ald1[NN * 8];
__device__ __nv_bfloat162 g_xw2b[NN * 64];   // xw2 values, bf16 (128 feats/node)
__device__ float g_als2[NN];
__device__ float g_ald2[NN];
__device__ float g_out2[NN * OUT];
__device__ float g_M1[ED * 8];
__device__ float g_m2[ED];
__device__ int   g_gptr[GG + 1];

// packed fp32x2 FMA (sm_10x): d = a*b + d, two fp32 lanes per instruction
__device__ __forceinline__ void ffma2(unsigned long long& d,
                                      unsigned long long a, unsigned long long b) {
    asm("fma.rn.f32x2 %0, %1, %2, %0;" : "+l"(d) : "l"(a), "l"(b));
}
__device__ __forceinline__ unsigned long long pack2(float v) {
    unsigned long long r;
    asm("mov.b64 %0, {%1, %1};" : "=l"(r) : "r"(__float_as_uint(v)));
    return r;
}
__device__ __forceinline__ float2 unpack2(unsigned long long p) {
    unsigned int lo, hi;
    asm("mov.b64 {%0, %1}, %2;" : "=r"(lo), "=r"(hi) : "l"(p));
    return make_float2(__uint_as_float(lo), __uint_as_float(hi));
}

// ---------------- kernels ----------------

// Fused setup: zero padded deg + reduced attention matrices + graph offsets.
__global__ void setup_kernel(const float* __restrict__ We1, const float* __restrict__ ae1,
                             const float* __restrict__ We2, const float* __restrict__ ae2,
                             const int* __restrict__ batch) {
    int i = blockIdx.x * blockDim.x + threadIdx.x;
    if (i < NPAD) g_deg[i] = 0;
    if (i < 128) {
        int d = i >> 3, h = i & 7;
        float s = 0.f;
        #pragma unroll
        for (int c = 0; c < 8; c++) s += We1[d * 64 + h * 8 + c] * ae1[h * 8 + c];
        g_M1[d * 8 + h] = s;
    }
    if (i < ED) {
        float s = 0.f;
        for (int c = 0; c < OUT; c++) s += We2[i * OUT + c] * ae2[c];
        g_m2[i] = s;
    }
    if (i <= GG) {
        if (i == GG) g_gptr[GG] = NN;
        else {
            int lo = 0, hi = NN;
            while (lo < hi) {
                int mid = (lo + hi) >> 1;
                if (batch[mid] < i) lo = mid + 1; else hi = mid;
            }
            g_gptr[i] = lo;
        }
    }
}

// Degree count: int4 dst load, 4 independent RED chains per thread.
__global__ void deg_kernel(const int* __restrict__ ei) {
    int e4 = blockIdx.x * blockDim.x + threadIdx.x;
    if (e4 < EE / 4) {
        int4 d = ((const int4*)(ei + EE))[e4];
        atomicAdd(&g_deg[d.x], 1);
        atomicAdd(&g_deg[d.y], 1);
        atomicAdd(&g_deg[d.z], 1);
        atomicAdd(&g_deg[d.w], 1);
    }
}

// Exclusive prefix sum of g_deg -> g_ptr, g_cursor. Single block, 1024 threads, int4.
__global__ void scan_kernel() {
    int t = threadIdx.x;
    const int4* dv = (const int4*)g_deg;
    int b4 = t * 13;            // 13 int4 = 52 ints per thread
    int sum = 0;
    #pragma unroll
    for (int k = 0; k < 13; k++) {
        int4 q = dv[b4 + k];
        sum += q.x + q.y + q.z + q.w;
    }
    int incl = sum;
    #pragma unroll
    for (int o = 1; o < 32; o <<= 1) {
        int u = __shfl_up_sync(0xffffffffu, incl, o);
        if ((t & 31) >= o) incl += u;
    }
    __shared__ int ws[32];
    if ((t & 31) == 31) ws[t >> 5] = incl;
    __syncthreads();
    if (t < 32) {
        int wv = ws[t];
        int wincl = wv;
        #pragma unroll
        for (int o = 1; o < 32; o <<= 1) {
            int u = __shfl_up_sync(0xffffffffu, wincl, o);
            if (t >= o) wincl += u;
        }
        ws[t] = wincl - wv;
    }
    __syncthreads();
    int run = ws[t >> 5] + (incl - sum);
    #pragma unroll
    for (int k = 0; k < 13; k++) {
        int4 q = dv[b4 + k];
        int i = t * 52 + k * 4;
        int4 p;
        p.x = run; p.y = run + q.x; p.z = p.y + q.y; p.w = p.z + q.z;
        run = p.w + q.w;
        if (i < NN) {                     // NN%4==0 so whole int4 in range
            ((int4*)g_ptr)[i >> 2] = p;
            ((int4*)g_cursor)[i >> 2] = p;
        }
    }
    if (t == 0) g_ptr[NN] = EE;
}

// Fused CSR scatter + edge-logit compute. Per thread: 4 edges.
// ea is read COALESCED in original edge order; logits scatter-written to CSR slots.
__global__ __launch_bounds__(256) void scatter_kernel(const int* __restrict__ ei,
                                                      const float* __restrict__ ea) {
    __shared__ float sM1[ED * 8];
    __shared__ float sm2[ED];
    if (threadIdx.x < 128) sM1[threadIdx.x] = g_M1[threadIdx.x];
    if (threadIdx.x < ED) sm2[threadIdx.x] = g_m2[threadIdx.x];
    __syncthreads();
    int e4 = blockIdx.x * blockDim.x + threadIdx.x;
    if (e4 >= EE / 4) return;
    int4 s4 = ((const int4*)ei)[e4];
    int4 d4 = ((const int4*)(ei + EE))[e4];
    int srcs[4] = {s4.x, s4.y, s4.z, s4.w};
    int dsts[4] = {d4.x, d4.y, d4.z, d4.w};
    int pos[4];
    #pragma unroll
    for (int k = 0; k < 4; k++)
        pos[k] = atomicAdd(&g_cursor[dsts[k]], 1);   // 4 overlapping ATOMG chains
    #pragma unroll
    for (int k = 0; k < 4; k++) {
        int e = e4 * 4 + k;
        const float4* p = (const float4*)(ea + (size_t)e * ED);
        float4 q0 = p[0], q1 = p[1], q2 = p[2], q3 = p[3];
        float av[16] = {q0.x, q0.y, q0.z, q0.w, q1.x, q1.y, q1.z, q1.w,
                        q2.x, q2.y, q2.z, q2.w, q3.x, q3.y, q3.z, q3.w};
        float r[8] = {0, 0, 0, 0, 0, 0, 0, 0};
        float r2 = 0.f;
        #pragma unroll
        for (int d = 0; d < ED; d++) {
            float a = av[d];
            #pragma unroll
            for (int h = 0; h < 8; h++) r[h] += a * sM1[d * 8 + h];
            r2 += a * sm2[d];
        }
        int pk = pos[k];
        g_srcCSR[pk] = srcs[k];
        float4* o = (float4*)(g_alE1 + (size_t)pk * 8);
        o[0] = make_float4(r[0], r[1], r[2], r[3]);
        o[1] = make_float4(r[4], r[5], r[6], r[7]);
        g_alE2[pk] = r2;
    }
}

// xw1 = x @ W1 (bf16 out), plus per-node attention scalars als1/ald1 (fp32).
// Register-blocked: 64 nodes/block, 4 nodes/thread, packed f32x2 FMAs.
#define G1_NODES 64
__global__ __launch_bounds__(256) void gemm1_kernel(const float* __restrict__ x,
                             const float* __restrict__ W1,
                             const float* __restrict__ as1, const float* __restrict__ ad1) {
    __shared__ float xs[G1_NODES][FIN + 4];   // pitch 132: kills stride-128 bank conflicts
    int n0 = blockIdx.x * G1_NODES;
    // stage x (clamped for the tail block)
    for (int idx = threadIdx.x; idx < G1_NODES * (FIN / 4); idx += 256) {
        int row = idx >> 5;          // FIN/4 = 32 float4 per row
        int c4  = idx & 31;
        int n = n0 + row; if (n >= NN) n = NN - 1;
        float4 v = ((const float4*)(x + (size_t)n * FIN))[c4];
        *(float4*)&xs[row][c4 * 4] = v;
    }
    __syncthreads();
    int jg = threadIdx.x & 15;   // float4 column group (4 of 64 outputs)
    int ng = threadIdx.x >> 4;   // node group: nodes n0 + ng*4 .. +3
    const ulonglong2* W1v = (const ulonglong2*)W1;   // row = 16 x (2 f32x2)
    unsigned long long a0[4], a1[4];
    #pragma unroll
    for (int i = 0; i < 4; i++) { a0[i] = 0ull; a1[i] = 0ull; }
    #pragma unroll 4
    for (int k = 0; k < FIN; k++) {
        ulonglong2 w = W1v[k * 16 + jg];
        #pragma unroll
        for (int i = 0; i < 4; i++) {
            unsigned long long xv = pack2(xs[ng * 4 + i][k]);
            ffma2(a0[i], xv, w.x);
            ffma2(a1[i], xv, w.y);
        }
    }
    float4 a_s = ((const float4*)as1)[jg];
    float4 a_d = ((const float4*)ad1)[jg];
    #pragma unroll
    for (int i = 0; i < 4; i++) {
        int n = n0 + ng * 4 + i;
        if (n >= NN) break;
        float2 lo = unpack2(a0[i]);
        float2 hi = unpack2(a1[i]);
        __nv_bfloat162 c0 = __float22bfloat162_rn(lo);
        __nv_bfloat162 c1 = __float22bfloat162_rn(hi);
        uint2 pk;
        pk.x = *(unsigned int*)&c0;
        pk.y = *(unsigned int*)&c1;
        ((uint2*)(g_xw1b + (size_t)n * 32))[jg] = pk;
        float ps = lo.x * a_s.x + lo.y * a_s.y + hi.x * a_s.z + hi.y * a_s.w;
        float pd = lo.x * a_d.x + lo.y * a_d.y + hi.x * a_d.z + hi.y * a_d.w;
        ps += __shfl_xor_sync(0xffffffffu, ps, 1);
        pd += __shfl_xor_sync(0xffffffffu, pd, 1);
        if ((threadIdx.x & 1) == 0) {
            int h = jg >> 1;
            g_als1[n * 8 + h] = ps;
            g_ald1[n * 8 + h] = pd;
        }
    }
}

// Layer-1 softmax + aggregation + ELU, fused with gemm2 and self-loop fold.
// One warp per node. Lane l: computes logits for head l&7; owns features 2l,2l+1
// (value head l>>2, one bf16x2 load per edge).
__global__ __launch_bounds__(256) void agg1_kernel(const float* __restrict__ b1,
        const float* __restrict__ W2,
        const float* __restrict__ as2, const float* __restrict__ ad2) {
    __shared__ float hs[8][HID];
    int warp = threadIdx.x >> 5;
    int n = blockIdx.x * 8 + warp;           // NN % 8 == 0
    int l = threadIdx.x & 31;
    int h8 = l & 7;
    int hv = l >> 2;                          // value head for features 2l,2l+1
    const float* __restrict__ als1 = g_als1;
    const float* __restrict__ alE1 = g_alE1;
    const __nv_bfloat162* __restrict__ xw1b = g_xw1b;
    const int* __restrict__ srcv = g_srcCSR;

    float ald   = g_ald1[n * 8 + h8];
    float myals = als1[n * 8 + h8];
    int beg = g_ptr[n], end = g_ptr[n + 1];

    float s = 0.f, salE = 0.f;
    float acc0 = 0.f, acc1 = 0.f;
    int j = beg;
    for (; j + 1 < end; j += 2) {
        int sA = srcv[j], sB = srcv[j + 1];
        float alsA = als1[sA * 8 + h8];
        float alsB = als1[sB * 8 + h8];
        float aleA = alE1[(size_t)j * 8 + h8];
        float aleB = alE1[(size_t)(j + 1) * 8 + h8];
        __nv_bfloat162 vA = xw1b[(size_t)sA * 32 + l];
        __nv_bfloat162 vB = xw1b[(size_t)sB * 32 + l];
        salE += aleA + aleB;
        float zA = alsA + ald + aleA; zA = zA > 0.f ? zA : NEG * zA;
        float zB = alsB + ald + aleB; zB = zB > 0.f ? zB : NEG * zB;
        float eA = __expf(zA), eB = __expf(zB);
        s += eA + eB;
        float wA = __shfl_sync(0xffffffffu, eA, hv);
        float wB = __shfl_sync(0xffffffffu, eB, hv);
        float2 fA = __bfloat1622float2(vA);
        float2 fB = __bfloat1622float2(vB);
        acc0 += fA.x * wA; acc1 += fA.y * wA;
        acc0 += fB.x * wB; acc1 += fB.y * wB;
    }
    if (j < end) {
        int sA = srcv[j];
        float alsA = als1[sA * 8 + h8];
        float aleA = alE1[(size_t)j * 8 + h8];
        __nv_bfloat162 vA = xw1b[(size_t)sA * 32 + l];
        salE += aleA;
        float zA = alsA + ald + aleA; zA = zA > 0.f ? zA : NEG * zA;
        float eA = __expf(zA);
        s += eA;
        float wA = __shfl_sync(0xffffffffu, eA, hv);
        float2 fA = __bfloat1622float2(vA);
        acc0 += fA.x * wA; acc1 += fA.y * wA;
    }
    // self loop: edge logit = mean of incoming edge logits (salE is full per-head sum)
    float rd = 1.f / (float)max(end - beg, 1);
    float zs = myals + ald + salE * rd;
    zs = zs > 0.f ? zs : NEG * zs;
    float es = __expf(zs);
    s += es;
    float wsv = __shfl_sync(0xffffffffu, es, hv);
    float2 fS = __bfloat1622float2(xw1b[(size_t)n * 32 + l]);
    acc0 += fS.x * wsv; acc1 += fS.y * wsv;
    // s is already the full per-head denominator
    float sv = __shfl_sync(0xffffffffu, s, hv);
    float2 bb = ((const float2*)b1)[l];
    float o0 = acc0 / (sv + 1e-16f) + bb.x;
    float o1 = acc1 / (sv + 1e-16f) + bb.y;
    o0 = o0 > 0.f ? o0 : (__expf(o0) - 1.f);   // ELU
    o1 = o1 > 0.f ? o1 : (__expf(o1) - 1.f);
    hs[warp][2 * l] = o0;
    hs[warp][2 * l + 1] = o1;
    __syncthreads();

    // ---- fused gemm2: xw2[n] = h[n] @ W2 (bf16 out), plus als2/ald2 scalars ----
    const float4* W2v = (const float4*)W2;
    float4 acc = make_float4(0.f, 0.f, 0.f, 0.f);
    #pragma unroll 8
    for (int k = 0; k < HID; k++) {
        float hv2 = hs[warp][k];
        float4 w = W2v[k * 32 + l];
        acc.x += hv2 * w.x; acc.y += hv2 * w.y; acc.z += hv2 * w.z; acc.w += hv2 * w.w;
    }
    __nv_bfloat162 c0 = __float22bfloat162_rn(make_float2(acc.x, acc.y));
    __nv_bfloat162 c1 = __float22bfloat162_rn(make_float2(acc.z, acc.w));
    uint2 pk;
    pk.x = *(unsigned int*)&c0;
    pk.y = *(unsigned int*)&c1;
    ((uint2*)(g_xw2b + (size_t)n * 64))[l] = pk;
    float4 a_s = ((const float4*)as2)[l];
    float4 a_d = ((const float4*)ad2)[l];
    float ps = acc.x * a_s.x + acc.y * a_s.y + acc.z * a_s.z + acc.w * a_s.w;
    float pd = acc.x * a_d.x + acc.y * a_d.y + acc.z * a_d.z + acc.w * a_d.w;
    #pragma unroll
    for (int o = 16; o > 0; o >>= 1) {
        ps += __shfl_xor_sync(0xffffffffu, ps, o);
        pd += __shfl_xor_sync(0xffffffffu, pd, o);
    }
    if (l == 0) {
        g_als2[n] = ps;
        g_ald2[n] = pd;
    }
}

// Layer-2 softmax + aggregation with fused self-loop; one warp per node,
// lane owns features 4l..4l+3 via one 8B bf16 load per edge.
__global__ __launch_bounds__(256) void agg2_kernel(const float* __restrict__ b2) {
    int warp = (blockIdx.x * blockDim.x + threadIdx.x) >> 5;
    if (warp >= NN) return;
    int n = warp;
    int l = threadIdx.x & 31;
    const uint2* __restrict__ xw = (const uint2*)g_xw2b;
    const float* __restrict__ als2 = g_als2;
    const float* __restrict__ alE2 = g_alE2;
    const int*   __restrict__ srcv = g_srcCSR;
    float ald   = g_ald2[n];
    float myals = als2[n];
    int beg = g_ptr[n], end = g_ptr[n + 1];
    float s = 0.f, salE = 0.f;
    float4 acc = make_float4(0.f, 0.f, 0.f, 0.f);
    int j = beg;
    for (; j + 1 < end; j += 2) {
        int sA = srcv[j], sB = srcv[j + 1];
        float aleA = alE2[j], aleB = alE2[j + 1];
        float alsA = als2[sA], alsB = als2[sB];
        uint2 uA = xw[(size_t)sA * 32 + l];
        uint2 uB = xw[(size_t)sB * 32 + l];
        salE += aleA + aleB;
        float zA = alsA + ald + aleA; zA = zA > 0.f ? zA : NEG * zA;
        float zB = alsB + ald + aleB; zB = zB > 0.f ? zB : NEG * zB;
        float eA = __expf(zA), eB = __expf(zB);
        s += eA + eB;
        float2 fA0 = __bfloat1622float2(*(__nv_bfloat162*)&uA.x);
        float2 fA1 = __bfloat1622float2(*(__nv_bfloat162*)&uA.y);
        float2 fB0 = __bfloat1622float2(*(__nv_bfloat162*)&uB.x);
        float2 fB1 = __bfloat1622float2(*(__nv_bfloat162*)&uB.y);
        acc.x += fA0.x * eA; acc.y += fA0.y * eA; acc.z += fA1.x * eA; acc.w += fA1.y * eA;
        acc.x += fB0.x * eB; acc.y += fB0.y * eB; acc.z += fB1.x * eB; acc.w += fB1.y * eB;
    }
    if (j < end) {
        int sA = srcv[j];
        float aleA = alE2[j];
        float alsA = als2[sA];
        uint2 uA = xw[(size_t)sA * 32 + l];
        salE += aleA;
        float zA = alsA + ald + aleA; zA = zA > 0.f ? zA : NEG * zA;
        float eA = __expf(zA);
        s += eA;
        float2 fA0 = __bfloat1622float2(*(__nv_bfloat162*)&uA.x);
        float2 fA1 = __bfloat1622float2(*(__nv_bfloat162*)&uA.y);
        acc.x += fA0.x * eA; acc.y += fA0.y * eA; acc.z += fA1.x * eA; acc.w += fA1.y * eA;
    }
    // self loop
    float rd = 1.f / (float)max(end - beg, 1);
    float zs = myals + ald + salE * rd;
    zs = zs > 0.f ? zs : NEG * zs;
    float es = __expf(zs);
    s += es;
    uint2 uS = xw[(size_t)n * 32 + l];
    float2 fS0 = __bfloat1622float2(*(__nv_bfloat162*)&uS.x);
    float2 fS1 = __bfloat1622float2(*(__nv_bfloat162*)&uS.y);
    acc.x += fS0.x * es; acc.y += fS0.y * es; acc.z += fS1.x * es; acc.w += fS1.y * es;

    float inv = 1.f / (s + 1e-16f);
    float4 bb = ((const float4*)b2)[l];
    float4 o = make_float4(acc.x * inv + bb.x, acc.y * inv + bb.y,
                           acc.z * inv + bb.z, acc.w * inv + bb.w);
    ((float4*)g_out2)[(size_t)n * 32 + l] = o;
}

// Global mean pool: one block per graph; 512 threads = 4-way row split per feature.
__global__ void pool_kernel(float* __restrict__ out) {
    __shared__ float sm[4][128];
    int g = blockIdx.x;
    int f = threadIdx.x & 127;
    int part = threadIdx.x >> 7;
    int s = g_gptr[g], e = g_gptr[g + 1];
    float acc = 0.f;
    for (int n = s + part; n < e; n += 4) acc += g_out2[(size_t)n * OUT + f];
    sm[part][f] = acc;
    __syncthreads();
    if (part == 0)
        out[g * OUT + f] = (sm[0][f] + sm[1][f] + sm[2][f] + sm[3][f])
                           / fmaxf((float)(e - s), 1.f);
}

// ---------------- launch ----------------
extern "C" void kernel_launch(void* const* d_in, const int* in_sizes, int n_in,
                              void* d_out, int out_size) {
    const float* x     = (const float*)d_in[0];
    const int*   ei    = (const int*)d_in[1];
    const float* ea    = (const float*)d_in[2];
    const int*   batch = (const int*)d_in[3];
    const float* W1    = (const float*)d_in[4];
    const float* as1   = (const float*)d_in[5];
    const float* ad1   = (const float*)d_in[6];
    const float* ae1   = (const float*)d_in[7];
    const float* We1   = (const float*)d_in[8];
    const float* b1    = (const float*)d_in[9];
    const float* W2    = (const float*)d_in[10];
    const float* as2   = (const float*)d_in[11];
    const float* ad2   = (const float*)d_in[12];
    const float* ae2   = (const float*)d_in[13];
    const float* We2   = (const float*)d_in[14];
    const float* b2    = (const float*)d_in[15];
    float* out = (float*)d_out;

    setup_kernel<<<NPAD / 256, 256>>>(We1, ae1, We2, ae2, batch);
    deg_kernel<<<(EE / 4 + 255) / 256, 256>>>(ei);
    scan_kernel<<<1, 1024>>>();
    gemm1_kernel<<<(NN + G1_NODES - 1) / G1_NODES, 256>>>(x, W1, as1, ad1);
    scatter_kernel<<<(EE / 4 + 255) / 256, 256>>>(ei, ea);
    agg1_kernel<<<NN / 8, 256>>>(b1, W2, as2, ad2);
    agg2_kernel<<<NN / 8, 256>>>(b2);
    pool_kernel<<<GG, 512>>>(out);
}